// round 11
// baseline (speedup 1.0000x reference)
#include <cuda_runtime.h>
#include <cstdint>

typedef unsigned int uint;

// ---------------- static device scratch (no allocs allowed) ----------------
__device__ float g_wscale[4];                 // s1, s2, s3, sc
__device__ float g_w1q[32*3*3*3];             // quantized fp32 conv1 weights (OIHW)
__device__ uint  g_w2p[64*9*8];               // [oc][tap][ic/4] packed s8 {-1,0,1}
__device__ uint  g_w3p[128*9*16];             // [oc][tap][ic/4]
__device__ uint  g_wcp[10*32];                // [oc][ic/4]
// activation codes (0..3) in NHWC, 1 byte/elem, viewed as uint4 for alignment
__device__ uint4 g_h1[32*112*112*32/16];      // 12.85 MB
__device__ uint4 g_h2[32*56*56*64/16];        //  6.42 MB
__device__ uint4 g_h3[32*28*28*128/16];       //  3.21 MB

// ---------------- kernel 0: per-tensor max-abs weight scales ----------------
__global__ void k_scales(const float* __restrict__ w1, const float* __restrict__ w2,
                         const float* __restrict__ w3, const float* __restrict__ wc) {
    const float* ptrs[4] = {w1, w2, w3, wc};
    const int    ns[4]   = {864, 18432, 73728, 1280};
    int r = blockIdx.x;
    const float* w = ptrs[r];
    int n = ns[r];
    float m = 0.f;
    for (int i = threadIdx.x; i < n; i += blockDim.x) m = fmaxf(m, fabsf(w[i]));
    __shared__ float s[256];
    s[threadIdx.x] = m;
    __syncthreads();
    for (int o = 128; o > 0; o >>= 1) {
        if (threadIdx.x < o) s[threadIdx.x] = fmaxf(s[threadIdx.x], s[threadIdx.x + o]);
        __syncthreads();
    }
    if (threadIdx.x == 0) g_wscale[r] = fmaxf(s[0], 1e-8f);  // qmax = 2^(2-1)-1 = 1
}

// ---------------- kernel 1: quantize + pack weights ----------------
__global__ void k_pack(const float* __restrict__ w1, const float* __restrict__ w2,
                       const float* __restrict__ w3, const float* __restrict__ wc) {
    int i = blockIdx.x * blockDim.x + threadIdx.x;
    if (i < 864) {
        float s = g_wscale[0];
        g_w1q[i] = rintf(__fdiv_rn(w1[i], s)) * s;     // round-half-even, like jnp.round
    } else if (i < 864 + 4608) {
        int k = i - 864;
        float s = g_wscale[1];
        int oc = k / 72, r = k % 72, tap = r / 8, j = r % 8;
        int ty = tap / 3, tx = tap % 3;
        uint pk = 0;
        #pragma unroll
        for (int kk = 0; kk < 4; kk++) {
            int ic = 4*j + kk;
            int q = (int)rintf(__fdiv_rn(w2[((oc*32 + ic)*3 + ty)*3 + tx], s));
            pk |= ((uint)(unsigned char)(signed char)q) << (8*kk);
        }
        g_w2p[k] = pk;
    } else if (i < 864 + 4608 + 18432) {
        int k = i - (864 + 4608);
        float s = g_wscale[2];
        int oc = k / 144, r = k % 144, tap = r / 16, j = r % 16;
        int ty = tap / 3, tx = tap % 3;
        uint pk = 0;
        #pragma unroll
        for (int kk = 0; kk < 4; kk++) {
            int ic = 4*j + kk;
            int q = (int)rintf(__fdiv_rn(w3[((oc*64 + ic)*3 + ty)*3 + tx], s));
            pk |= ((uint)(unsigned char)(signed char)q) << (8*kk);
        }
        g_w3p[k] = pk;
    } else if (i < 864 + 4608 + 18432 + 320) {
        int k = i - (864 + 4608 + 18432);
        float s = g_wscale[3];
        int oc = k / 32, j = k % 32;
        uint pk = 0;
        #pragma unroll
        for (int kk = 0; kk < 4; kk++) {
            int q = (int)rintf(__fdiv_rn(wc[oc*128 + 4*j + kk], s));
            pk |= ((uint)(unsigned char)(signed char)q) << (8*kk);
        }
        g_wcp[k] = pk;
    }
}

// ---------------- kernel 2: conv1 (fp32) + quant_act + maxpool2, fused ----------------
// Block: 16x16 pooled outputs of one batch, all 32 output channels.
// quant is monotone -> pool conv outputs first, quantize once.
__global__ __launch_bounds__(256) void k_conv1(const float* __restrict__ x,
                                               const float* __restrict__ a1) {
    __shared__ float s_in[3*34*34];   // 34x34 input tile x 3 channels (with halo)
    __shared__ float s_w[864];
    int b  = blockIdx.z;
    int Y0 = blockIdx.y * 16, X0 = blockIdx.x * 16;   // pooled-coords tile origin

    for (int i = threadIdx.x; i < 864; i += 256) s_w[i] = g_w1q[i];
    for (int i = threadIdx.x; i < 3*34*34; i += 256) {
        int ic = i / 1156, rem = i % 1156, r = rem / 34, c = rem % 34;
        int gy = 2*Y0 - 1 + r, gx = 2*X0 - 1 + c;
        float v = 0.f;
        if ((unsigned)gy < 224u && (unsigned)gx < 224u)
            v = x[((b*3 + ic)*224 + gy)*224 + gx];
        s_in[i] = v;
    }
    __syncthreads();

    int sy = threadIdx.x >> 4, sx = threadIdx.x & 15;
    float p[3][4][4];                                  // 4x4 input patch per channel
    #pragma unroll
    for (int ic = 0; ic < 3; ic++)
        #pragma unroll
        for (int u = 0; u < 4; u++)
            #pragma unroll
            for (int v = 0; v < 4; v++)
                p[ic][u][v] = s_in[ic*1156 + (2*sy + u)*34 + (2*sx + v)];

    float alpha = a1[0];
    float qs = __fdiv_rn(alpha, 3.0f);                 // scale = alpha / (2^2 - 1)
    uint* h1u = (uint*)g_h1;
    int pixbase = ((b*112 + (Y0 + sy))*112 + (X0 + sx)) * 8;

    #pragma unroll 1
    for (int og = 0; og < 8; og++) {                   // 8 groups of 4 output channels
        uint pk = 0;
        #pragma unroll
        for (int oo = 0; oo < 4; oo++) {
            int oc = og*4 + oo;
            float a00 = 0.f, a01 = 0.f, a10 = 0.f, a11 = 0.f;
            #pragma unroll
            for (int ic = 0; ic < 3; ic++)
                #pragma unroll
                for (int ty = 0; ty < 3; ty++)
                    #pragma unroll
                    for (int tx = 0; tx < 3; tx++) {
                        float w = s_w[oc*27 + ic*9 + ty*3 + tx];
                        a00 = fmaf(w, p[ic][ty  ][tx  ], a00);
                        a01 = fmaf(w, p[ic][ty  ][tx+1], a01);
                        a10 = fmaf(w, p[ic][ty+1][tx  ], a10);
                        a11 = fmaf(w, p[ic][ty+1][tx+1], a11);
                    }
            float v = fmaxf(fmaxf(a00, a01), fmaxf(a10, a11));   // maxpool first
            float y = fminf(fmaxf(v, 0.f), alpha);
            uint code = (uint)(int)rintf(__fdiv_rn(y, qs));      // PACT fake-quant code
            pk |= code << (8*oo);
        }
        h1u[pixbase + og] = pk;
    }
}

// ---------------- kernels 3/4: int8 dp4a conv + quant + maxpool, fused ----------------
// LAYER=2: 112->56, IC=32, OC=64.  LAYER=3: 56->28, IC=64, OC=128.
// Thread = one pooled spatial position x 8 output channels.
template<int LAYER>
__global__ __launch_bounds__(256) void k_convq(const float* __restrict__ a_prev,
                                               const float* __restrict__ a_cur) {
    constexpr int H_OUT   = (LAYER == 2) ? 56 : 28;
    constexpr int TILE_PX = (LAYER == 2) ? 8  : 7;
    constexpr int IC_U4   = (LAYER == 2) ? 2  : 4;   // uint4s per pixel (16B = 16 ch)
    constexpr int OC_TOTAL= (LAYER == 2) ? 64 : 128;
    constexpr int H_IN    = 2 * H_OUT;
    constexpr int W_T     = 2*TILE_PX + 2;           // input tile width (pixels)
    constexpr int SPATIAL = 4 * TILE_PX;             // pooled positions per block
    const int wsi = (LAYER == 2) ? 1 : 2;

    const uint4* in4 = (LAYER == 2) ? g_h1 : g_h2;
    const uint4* wp4 = (LAYER == 2) ? (const uint4*)g_w2p : (const uint4*)g_w3p;
    uint* out_u      = (LAYER == 2) ? (uint*)g_h2 : (uint*)g_h3;

    __shared__ uint4 s_w[64*9*IC_U4];
    __shared__ uint4 s_in[10*W_T*IC_U4];

    int b, ochalf;
    if (OC_TOTAL == 64) { b = blockIdx.z; ochalf = 0; }
    else                { b = blockIdx.z >> 1; ochalf = blockIdx.z & 1; }
    int X0 = blockIdx.x * TILE_PX, Y0 = blockIdx.y * 4;

    for (int i = threadIdx.x; i < 64*9*IC_U4; i += blockDim.x)
        s_w[i] = wp4[ochalf*64*9*IC_U4 + i];
    for (int i = threadIdx.x; i < 10*W_T*IC_U4; i += blockDim.x) {
        int j = i % IC_U4, pix = i / IC_U4, r = pix / W_T, c = pix % W_T;
        int gy = 2*Y0 - 1 + r, gx = 2*X0 - 1 + c;
        uint4 v = make_uint4(0u, 0u, 0u, 0u);
        if ((unsigned)gy < (unsigned)H_IN && (unsigned)gx < (unsigned)H_IN)
            v = in4[((b*H_IN + gy)*H_IN + gx)*IC_U4 + j];
        s_in[i] = v;
    }
    __syncthreads();

    int sp = threadIdx.x % SPATIAL, ocg = threadIdx.x / SPATIAL;
    int sy = sp / TILE_PX, sx = sp % TILE_PX;

    int acc[2][2][8];
    #pragma unroll
    for (int py = 0; py < 2; py++)
        #pragma unroll
        for (int px = 0; px < 2; px++)
            #pragma unroll
            for (int oc = 0; oc < 8; oc++) acc[py][px][oc] = 0;

    #pragma unroll 1
    for (int ty = 0; ty < 3; ty++) {
        #pragma unroll 1
        for (int tx = 0; tx < 3; tx++) {
            uint4 pix[2][2][IC_U4];
            #pragma unroll
            for (int py = 0; py < 2; py++)
                #pragma unroll
                for (int px = 0; px < 2; px++)
                    #pragma unroll
                    for (int j = 0; j < IC_U4; j++)
                        pix[py][px][j] = s_in[((2*sy + py + ty)*W_T + (2*sx + px + tx))*IC_U4 + j];
            #pragma unroll
            for (int oc = 0; oc < 8; oc++) {
                #pragma unroll
                for (int j = 0; j < IC_U4; j++) {
                    uint4 w = s_w[((ocg*8 + oc)*9 + ty*3 + tx)*IC_U4 + j];
                    #pragma unroll
                    for (int py = 0; py < 2; py++)
                        #pragma unroll
                        for (int px = 0; px < 2; px++) {
                            int a = acc[py][px][oc];
                            a = __dp4a((int)pix[py][px][j].x, (int)w.x, a);
                            a = __dp4a((int)pix[py][px][j].y, (int)w.y, a);
                            a = __dp4a((int)pix[py][px][j].z, (int)w.z, a);
                            a = __dp4a((int)pix[py][px][j].w, (int)w.w, a);
                            acc[py][px][oc] = a;
                        }
                }
            }
        }
    }

    // conv value = (s_w * prev_act_scale) * int_acc ; pool (int max, scale>0) then quantize
    float scale = g_wscale[wsi] * __fdiv_rn(a_prev[0], 3.0f);
    float alpha = a_cur[0];
    float qs = __fdiv_rn(alpha, 3.0f);
    int Y = Y0 + sy, X = X0 + sx;
    uint pk0 = 0, pk1 = 0;
    #pragma unroll
    for (int oc = 0; oc < 8; oc++) {
        int m = max(max(acc[0][0][oc], acc[0][1][oc]), max(acc[1][0][oc], acc[1][1][oc]));
        float v = scale * (float)m;
        float y = fminf(fmaxf(v, 0.f), alpha);
        uint code = (uint)(int)rintf(__fdiv_rn(y, qs));
        if (oc < 4) pk0 |= code << (8*oc);
        else        pk1 |= code << (8*(oc - 4));
    }
    int ocfull = ochalf*64 + ocg*8;
    int base = ((b*H_OUT + Y)*H_OUT + X)*(OC_TOTAL/4) + ocfull/4;
    out_u[base]     = pk0;
    out_u[base + 1] = pk1;
}

// ---------------- kernel 5: global amax pool + 1x1 ternary classifier ----------------
__global__ void k_cls(const float* __restrict__ a3, float* __restrict__ out) {
    __shared__ uint s_part[4][32];
    __shared__ uint s_max[32];
    int b = blockIdx.x, t = threadIdx.x;
    const uint* h3u = (const uint*)g_h3;
    int quarter = t >> 5, ci = t & 31;          // ci: 4-channel group index
    uint m = 0;
    int p0 = quarter * 196;
    for (int p = p0; p < p0 + 196; p++)
        m = __vmaxu4(m, h3u[(b*784 + p)*32 + ci]);
    s_part[quarter][ci] = m;
    __syncthreads();
    if (t < 32)
        s_max[t] = __vmaxu4(__vmaxu4(s_part[0][t], s_part[1][t]),
                            __vmaxu4(s_part[2][t], s_part[3][t]));
    __syncthreads();
    if (t < 10) {
        int acc = 0;
        #pragma unroll
        for (int j = 0; j < 32; j++)
            acc = __dp4a((int)s_max[j], (int)g_wcp[t*32 + j], acc);
        float scale = g_wscale[3] * __fdiv_rn(a3[0], 3.0f);
        out[b*10 + t] = scale * (float)acc;
    }
}

// ---------------- launch ----------------
extern "C" void kernel_launch(void* const* d_in, const int* in_sizes, int n_in,
                              void* d_out, int out_size) {
    const float* x  = (const float*)d_in[0];
    const float* w1 = (const float*)d_in[1];
    const float* w2 = (const float*)d_in[2];
    const float* w3 = (const float*)d_in[3];
    const float* wc = (const float*)d_in[4];
    const float* a1 = (const float*)d_in[5];
    const float* a2 = (const float*)d_in[6];
    const float* a3 = (const float*)d_in[7];
    float* out = (float*)d_out;

    k_scales<<<4, 256>>>(w1, w2, w3, wc);
    k_pack<<<(24224 + 255)/256, 256>>>(w1, w2, w3, wc);
    k_conv1<<<dim3(7, 7, 32), 256>>>(x, a1);              // 112x112x32 pooled codes
    k_convq<2><<<dim3(7, 14, 32), 256>>>(a1, a2);         // 56x56x64
    k_convq<3><<<dim3(4, 7, 64), 224>>>(a2, a3);          // 28x28x128 (2 oc-halves)
    k_cls<<<32, 128>>>(a3, out);
}

// round 12
// speedup vs baseline: 1.4690x; 1.4690x over previous
#include <cuda_runtime.h>
#include <cstdint>

typedef unsigned int uint;

// ---------------- static device scratch (no allocs allowed) ----------------
__device__ float g_wscale[4];                 // s1, s2, s3, sc
__device__ float g_w1q[32*3*3*3];             // quantized fp32 conv1 weights (OIHW)
__device__ uint  g_w2f[4608];                 // layer2 weights in IMMA A-frag order
__device__ uint  g_w3f[18432];                // layer3 weights in IMMA A-frag order
__device__ uint  g_wcp[10*32];                // [oc][ic/4] classifier packed s8
// activation codes (0..3) in NHWC, 1 byte/elem
__device__ uint4 g_h1[32*112*112*32/16];      // 12.85 MB
__device__ uint4 g_h2[32*56*56*64/16];        //  6.42 MB
__device__ uint4 g_h3[32*28*28*128/16];       //  3.21 MB

// ---------------- IMMA helper ----------------
__device__ __forceinline__ void mma_s8(int* c, uint a0, uint a1, uint a2, uint a3,
                                       uint b0, uint b1) {
    asm volatile(
        "mma.sync.aligned.m16n8k32.row.col.s32.s8.s8.s32 "
        "{%0,%1,%2,%3}, {%4,%5,%6,%7}, {%8,%9}, {%0,%1,%2,%3};\n"
        : "+r"(c[0]), "+r"(c[1]), "+r"(c[2]), "+r"(c[3])
        : "r"(a0), "r"(a1), "r"(a2), "r"(a3), "r"(b0), "r"(b1));
}

// ---------------- kernel 0: per-tensor max-abs weight scales ----------------
__global__ void k_scales(const float* __restrict__ w1, const float* __restrict__ w2,
                         const float* __restrict__ w3, const float* __restrict__ wc) {
    const float* ptrs[4] = {w1, w2, w3, wc};
    const int    ns[4]   = {864, 18432, 73728, 1280};
    int r = blockIdx.x;
    const float* w = ptrs[r];
    int n = ns[r];
    float m = 0.f;
    for (int i = threadIdx.x; i < n; i += blockDim.x) m = fmaxf(m, fabsf(w[i]));
    __shared__ float s[256];
    s[threadIdx.x] = m;
    __syncthreads();
    for (int o = 128; o > 0; o >>= 1) {
        if (threadIdx.x < o) s[threadIdx.x] = fmaxf(s[threadIdx.x], s[threadIdx.x + o]);
        __syncthreads();
    }
    if (threadIdx.x == 0) g_wscale[r] = fmaxf(s[0], 1e-8f);  // qmax = 2^(2-1)-1 = 1
}

// ---------------- kernel 1: quantize + pack weights (IMMA fragment order) ---------
// A-frag for m16n8k32 (row-major): lane = g*4+q (g=lane>>2,q=lane&3);
//   word r=0: row g,   k bytes 4q..4q+3  (chunk 0: k 0-15)
//   word r=1: row g+8, chunk 0
//   word r=2: row g,   chunk 1 (k 16-31)
//   word r=3: row g+8, chunk 1
__global__ void k_pack(const float* __restrict__ w1, const float* __restrict__ w2,
                       const float* __restrict__ w3, const float* __restrict__ wc) {
    int i = blockIdx.x * blockDim.x + threadIdx.x;
    if (i < 864) {
        float s = g_wscale[0];
        g_w1q[i] = rintf(__fdiv_rn(w1[i], s)) * s;     // round-half-even, like jnp.round
    } else if (i < 864 + 4608) {
        // layer2: g_w2f word k; uint4 element e=(m*9+tap)*32+lane, word r
        int k = i - 864;
        float s = g_wscale[1];
        int e = k >> 2, r = k & 3;
        int lane = e & 31, tap = (e >> 5) % 9, m = e / 288;
        int oc  = m * 16 + (lane >> 2) + (r & 1) * 8;
        int ic0 = (r >> 1) * 16 + (lane & 3) * 4;
        int ty = tap / 3, tx = tap % 3;
        uint pk = 0;
        #pragma unroll
        for (int kk = 0; kk < 4; kk++) {
            int q = (int)rintf(__fdiv_rn(w2[((oc * 32 + ic0 + kk) * 3 + ty) * 3 + tx], s));
            pk |= ((uint)(unsigned char)(signed char)q) << (8 * kk);
        }
        g_w2f[k] = pk;
    } else if (i < 864 + 4608 + 18432) {
        // layer3: uint4 element e=((m*9+tap)*2+kc)*32+lane, word r
        int k = i - (864 + 4608);
        float s = g_wscale[2];
        int e = k >> 2, r = k & 3;
        int lane = e & 31;
        int kc  = (e >> 5) & 1;
        int tap = (e >> 6) % 9;
        int m   = e / 576;
        int oc  = m * 16 + (lane >> 2) + (r & 1) * 8;
        int ic0 = kc * 32 + (r >> 1) * 16 + (lane & 3) * 4;
        int ty = tap / 3, tx = tap % 3;
        uint pk = 0;
        #pragma unroll
        for (int kk = 0; kk < 4; kk++) {
            int q = (int)rintf(__fdiv_rn(w3[((oc * 64 + ic0 + kk) * 3 + ty) * 3 + tx], s));
            pk |= ((uint)(unsigned char)(signed char)q) << (8 * kk);
        }
        g_w3f[k] = pk;
    } else if (i < 864 + 4608 + 18432 + 320) {
        int k = i - (864 + 4608 + 18432);
        float s = g_wscale[3];
        int oc = k / 32, j = k % 32;
        uint pk = 0;
        #pragma unroll
        for (int kk = 0; kk < 4; kk++) {
            int q = (int)rintf(__fdiv_rn(wc[oc * 128 + 4 * j + kk], s));
            pk |= ((uint)(unsigned char)(signed char)q) << (8 * kk);
        }
        g_wcp[k] = pk;
    }
}

// ---------------- kernel 2: conv1 (fp32) + quant_act + maxpool2, fused ----------------
__global__ __launch_bounds__(256) void k_conv1(const float* __restrict__ x,
                                               const float* __restrict__ a1) {
    __shared__ float s_in[3*34*34];
    __shared__ float s_w[864];
    int b  = blockIdx.z;
    int Y0 = blockIdx.y * 16, X0 = blockIdx.x * 16;

    for (int i = threadIdx.x; i < 864; i += 256) s_w[i] = g_w1q[i];
    for (int i = threadIdx.x; i < 3*34*34; i += 256) {
        int ic = i / 1156, rem = i % 1156, r = rem / 34, c = rem % 34;
        int gy = 2*Y0 - 1 + r, gx = 2*X0 - 1 + c;
        float v = 0.f;
        if ((unsigned)gy < 224u && (unsigned)gx < 224u)
            v = x[((b*3 + ic)*224 + gy)*224 + gx];
        s_in[i] = v;
    }
    __syncthreads();

    int sy = threadIdx.x >> 4, sx = threadIdx.x & 15;
    float p[3][4][4];
    #pragma unroll
    for (int ic = 0; ic < 3; ic++)
        #pragma unroll
        for (int u = 0; u < 4; u++)
            #pragma unroll
            for (int v = 0; v < 4; v++)
                p[ic][u][v] = s_in[ic*1156 + (2*sy + u)*34 + (2*sx + v)];

    float alpha = a1[0];
    float qs = __fdiv_rn(alpha, 3.0f);
    uint* h1u = (uint*)g_h1;
    int pixbase = ((b*112 + (Y0 + sy))*112 + (X0 + sx)) * 8;

    #pragma unroll 1
    for (int og = 0; og < 8; og++) {
        uint pk = 0;
        #pragma unroll
        for (int oo = 0; oo < 4; oo++) {
            int oc = og*4 + oo;
            float a00 = 0.f, a01 = 0.f, a10 = 0.f, a11 = 0.f;
            #pragma unroll
            for (int ic = 0; ic < 3; ic++)
                #pragma unroll
                for (int ty = 0; ty < 3; ty++)
                    #pragma unroll
                    for (int tx = 0; tx < 3; tx++) {
                        float w = s_w[oc*27 + ic*9 + ty*3 + tx];
                        a00 = fmaf(w, p[ic][ty  ][tx  ], a00);
                        a01 = fmaf(w, p[ic][ty  ][tx+1], a01);
                        a10 = fmaf(w, p[ic][ty+1][tx  ], a10);
                        a11 = fmaf(w, p[ic][ty+1][tx+1], a11);
                    }
            float v = fmaxf(fmaxf(a00, a01), fmaxf(a10, a11));
            float y = fminf(fmaxf(v, 0.f), alpha);
            uint code = (uint)(int)rintf(__fdiv_rn(y, qs));
            pk |= code << (8*oo);
        }
        h1u[pixbase + og] = pk;
    }
}

// ---------------- kernel 3: conv2 via IMMA (M=oc16, N=x8, K=ic32) ----------------
// CTA = (pooled row Y, batch b). 8 warps: warp = xh (x half) * mtile(4).
// Each warp: 2 conv rows x 56 conv x (7 n-tiles) x 16 oc, 9 taps.
__global__ __launch_bounds__(256) void k_mma2(const float* __restrict__ a_prev,
                                              const float* __restrict__ a_cur) {
    __shared__ uint4 s4[4*114*3];   // 4 rows x 114 pixels x 48B pitch (32B data)
    uint* sw = (uint*)s4;
    int Y = blockIdx.x, b = blockIdx.y;
    int tid = threadIdx.x;

    for (int j = tid; j < 912; j += 256) {
        int row = j / 228, rem = j % 228, pix = rem >> 1, half = rem & 1;
        int gy = 2*Y - 1 + row, gx = pix - 1;
        uint4 v = make_uint4(0u,0u,0u,0u);
        if ((unsigned)gy < 112u && (unsigned)gx < 112u)
            v = g_h1[((b*112 + gy)*112 + gx)*2 + half];
        s4[(row*114 + pix)*3 + half] = v;
    }
    __syncthreads();

    int warp = tid >> 5, lane = tid & 31;
    int xh = warp & 1, m = warp >> 1;
    int g = lane >> 2, q = lane & 3;

    int acc[2][7][4];
    #pragma unroll
    for (int y = 0; y < 2; y++)
        #pragma unroll
        for (int nt = 0; nt < 7; nt++)
            #pragma unroll
            for (int k = 0; k < 4; k++) acc[y][nt][k] = 0;

    const uint4* wf = (const uint4*)g_w2f;
    #pragma unroll 1
    for (int tap = 0; tap < 9; tap++) {
        uint4 wv = wf[(m*9 + tap)*32 + lane];
        int ty = tap / 3, tx = tap % 3;
        #pragma unroll
        for (int y = 0; y < 2; y++) {
            int rowbase = (y + ty)*114;
            #pragma unroll
            for (int nt = 0; nt < 7; nt++) {
                int pix = xh*56 + nt*8 + g + tx;
                int w0 = (rowbase + pix)*12 + q;     // 48B pitch -> conflict-free
                uint b0 = sw[w0], b1 = sw[w0 + 4];
                mma_s8(acc[y][nt], wv.x, wv.y, wv.z, wv.w, b0, b1);
            }
        }
    }

    float scale = g_wscale[1] * __fdiv_rn(a_prev[0], 3.0f);
    float alpha = a_cur[0];
    float qs = __fdiv_rn(alpha, 3.0f);
    char* out = (char*)g_h2;
    #pragma unroll
    for (int nt = 0; nt < 7; nt++) {
        int v0 = max(max(acc[0][nt][0], acc[0][nt][1]), max(acc[1][nt][0], acc[1][nt][1]));
        int v1 = max(max(acc[0][nt][2], acc[0][nt][3]), max(acc[1][nt][2], acc[1][nt][3]));
        int X = xh*28 + nt*4 + q;
        int base = ((b*56 + Y)*56 + X)*64 + m*16 + g;
        float y0 = fminf(fmaxf(scale*(float)v0, 0.f), alpha);
        float y1 = fminf(fmaxf(scale*(float)v1, 0.f), alpha);
        out[base]     = (char)(int)rintf(__fdiv_rn(y0, qs));
        out[base + 8] = (char)(int)rintf(__fdiv_rn(y1, qs));
    }
}

// ---------------- kernel 4: conv3 via IMMA (IC=64 -> 2 k-chunks per tap) ----------------
// CTA = (pooled row Y, batch b). 8 warps: warp = mtile (oc group of 16).
__global__ __launch_bounds__(256) void k_mma3(const float* __restrict__ a_prev,
                                              const float* __restrict__ a_cur) {
    __shared__ uint4 s4[4*58*5];    // 4 rows x 58 pixels x 80B pitch (64B data)
    uint* sw = (uint*)s4;
    int Y = blockIdx.x, b = blockIdx.y;
    int tid = threadIdx.x;

    for (int j = tid; j < 928; j += 256) {
        int row = j / 232, rem = j % 232, pix = rem >> 2, qq = rem & 3;
        int gy = 2*Y - 1 + row, gx = pix - 1;
        uint4 v = make_uint4(0u,0u,0u,0u);
        if ((unsigned)gy < 56u && (unsigned)gx < 56u)
            v = g_h2[((b*56 + gy)*56 + gx)*4 + qq];
        s4[(row*58 + pix)*5 + qq] = v;
    }
    __syncthreads();

    int warp = tid >> 5, lane = tid & 31;
    int m = warp;
    int g = lane >> 2, q = lane & 3;

    int acc[2][7][4];
    #pragma unroll
    for (int y = 0; y < 2; y++)
        #pragma unroll
        for (int nt = 0; nt < 7; nt++)
            #pragma unroll
            for (int k = 0; k < 4; k++) acc[y][nt][k] = 0;

    const uint4* wf = (const uint4*)g_w3f;
    #pragma unroll 1
    for (int tap = 0; tap < 9; tap++) {
        int ty = tap / 3, tx = tap % 3;
        #pragma unroll
        for (int kc = 0; kc < 2; kc++) {
            uint4 wv = wf[((m*9 + tap)*2 + kc)*32 + lane];
            #pragma unroll
            for (int y = 0; y < 2; y++) {
                int rowbase = (y + ty)*58;
                #pragma unroll
                for (int nt = 0; nt < 7; nt++) {
                    int pix = nt*8 + g + tx;
                    int w0 = (rowbase + pix)*20 + kc*8 + q;  // 80B pitch -> conflict-free
                    uint b0 = sw[w0], b1 = sw[w0 + 4];
                    mma_s8(acc[y][nt], wv.x, wv.y, wv.z, wv.w, b0, b1);
                }
            }
        }
    }

    float scale = g_wscale[2] * __fdiv_rn(a_prev[0], 3.0f);
    float alpha = a_cur[0];
    float qs = __fdiv_rn(alpha, 3.0f);
    char* out = (char*)g_h3;
    #pragma unroll
    for (int nt = 0; nt < 7; nt++) {
        int v0 = max(max(acc[0][nt][0], acc[0][nt][1]), max(acc[1][nt][0], acc[1][nt][1]));
        int v1 = max(max(acc[0][nt][2], acc[0][nt][3]), max(acc[1][nt][2], acc[1][nt][3]));
        int X = nt*4 + q;
        int base = ((b*28 + Y)*28 + X)*128 + m*16 + g;
        float y0 = fminf(fmaxf(scale*(float)v0, 0.f), alpha);
        float y1 = fminf(fmaxf(scale*(float)v1, 0.f), alpha);
        out[base]     = (char)(int)rintf(__fdiv_rn(y0, qs));
        out[base + 8] = (char)(int)rintf(__fdiv_rn(y1, qs));
    }
}

// ---------------- kernel 5: global amax pool + 1x1 ternary classifier ----------------
__global__ void k_cls(const float* __restrict__ a3, float* __restrict__ out) {
    __shared__ uint s_part[4][32];
    __shared__ uint s_max[32];
    int b = blockIdx.x, t = threadIdx.x;
    const uint* h3u = (const uint*)g_h3;
    int quarter = t >> 5, ci = t & 31;
    uint m = 0;
    int p0 = quarter * 196;
    for (int p = p0; p < p0 + 196; p++)
        m = __vmaxu4(m, h3u[(b*784 + p)*32 + ci]);
    s_part[quarter][ci] = m;
    __syncthreads();
    if (t < 32)
        s_max[t] = __vmaxu4(__vmaxu4(s_part[0][t], s_part[1][t]),
                            __vmaxu4(s_part[2][t], s_part[3][t]));
    __syncthreads();
    if (t < 10) {
        int acc = 0;
        #pragma unroll
        for (int j = 0; j < 32; j++)
            acc = __dp4a((int)s_max[j], (int)g_wcp[t*32 + j], acc);
        float scale = g_wscale[3] * __fdiv_rn(a3[0], 3.0f);
        out[b*10 + t] = scale * (float)acc;
    }
}

// ---------------- launch ----------------
extern "C" void kernel_launch(void* const* d_in, const int* in_sizes, int n_in,
                              void* d_out, int out_size) {
    const float* x  = (const float*)d_in[0];
    const float* w1 = (const float*)d_in[1];
    const float* w2 = (const float*)d_in[2];
    const float* w3 = (const float*)d_in[3];
    const float* wc = (const float*)d_in[4];
    const float* a1 = (const float*)d_in[5];
    const float* a2 = (const float*)d_in[6];
    const float* a3 = (const float*)d_in[7];
    float* out = (float*)d_out;

    k_scales<<<4, 256>>>(w1, w2, w3, wc);
    k_pack<<<(24224 + 255)/256, 256>>>(w1, w2, w3, wc);
    k_conv1<<<dim3(7, 7, 32), 256>>>(x, a1);              // 112x112x32 pooled codes
    k_mma2<<<dim3(56, 32), 256>>>(a1, a2);                // 56x56x64 pooled codes
    k_mma3<<<dim3(28, 32), 256>>>(a2, a3);                // 28x28x128 pooled codes
    k_cls<<<32, 128>>>(a3, out);
}